// round 15
// baseline (speedup 1.0000x reference)
#include <cuda_runtime.h>
#include <cuda_bf16.h>
#include <cstdint>

#define BB   32
#define CC   1024
#define NSEQ 256
#define DQ   64
#define EPS_BN 1e-5f

typedef unsigned long long u64;
typedef unsigned int u32;

// ---------------- scratch (static device memory) ----------------
__device__ __nv_bfloat16 g_x_hi[(size_t)BB * CC * NSEQ];
__device__ __nv_bfloat16 g_x_lo[(size_t)BB * CC * NSEQ];
__device__ __nv_bfloat16 g_xT_hi[(size_t)BB * NSEQ * CC];
__device__ __nv_bfloat16 g_wv_hi[(size_t)CC * CC];
__device__ __nv_bfloat16 g_wqk_hi[128 * NSEQ];
__device__ __nv_bfloat16 g_wqk_lo[128 * NSEQ];
__device__ __nv_bfloat16 g_qT_hi[(size_t)BB * CC * DQ];
__device__ __nv_bfloat16 g_qT_lo[(size_t)BB * CC * DQ];
__device__ __nv_bfloat16 g_kT_hi[(size_t)BB * CC * DQ];
__device__ __nv_bfloat16 g_kT_lo[(size_t)BB * CC * DQ];
__device__ __nv_bfloat16 g_aff_hi[(size_t)BB * CC * CC];    // UNNORMALIZED exp
__device__ float         g_psum[(size_t)BB * CC * 8];
__device__ __nv_bfloat16 g_vT_hi[(size_t)BB * NSEQ * CC];

// ---------------- helpers ----------------
__device__ __forceinline__ u32 smem_u32(const void* p) {
    u32 a;
    asm("{ .reg .u64 t; cvta.to.shared.u64 t, %1; cvt.u32.u64 %0, t; }"
        : "=r"(a) : "l"(p));
    return a;
}
__device__ __forceinline__ void split_bf16(float v, __nv_bfloat16& h, __nv_bfloat16& l) {
    h = __float2bfloat16(v);
    l = __float2bfloat16(v - __bfloat162float(h));
}
__device__ __forceinline__ void cp16(u32 dst, const void* src) {
    asm volatile("cp.async.cg.shared.global [%0], [%1], 16;" :: "r"(dst), "l"(src));
}
__device__ __forceinline__ void cp_commit() {
    asm volatile("cp.async.commit_group;" ::: "memory");
}
__device__ __forceinline__ void cp_wait1() {
    asm volatile("cp.async.wait_group 1;" ::: "memory");
}
__device__ __forceinline__ void cp_wait0() {
    asm volatile("cp.async.wait_group 0;" ::: "memory");
}
__device__ __forceinline__ void ldsm4(u32 addr, u32& r0, u32& r1, u32& r2, u32& r3) {
    asm volatile("ldmatrix.sync.aligned.m8n8.x4.shared.b16 {%0,%1,%2,%3}, [%4];"
                 : "=r"(r0), "=r"(r1), "=r"(r2), "=r"(r3) : "r"(addr));
}
__device__ __forceinline__ void mma_bf16(float* c, const u32* a, u32 b0, u32 b1) {
    asm volatile(
        "mma.sync.aligned.m16n8k16.row.col.f32.bf16.bf16.f32 "
        "{%0,%1,%2,%3}, {%4,%5,%6,%7}, {%8,%9}, {%0,%1,%2,%3};"
        : "+f"(c[0]), "+f"(c[1]), "+f"(c[2]), "+f"(c[3])
        : "r"(a[0]), "r"(a[1]), "r"(a[2]), "r"(a[3]), "r"(b0), "r"(b1));
}

// =====================================================================
// convert_all (unchanged)
// =====================================================================
__global__ __launch_bounds__(256) void convert_all(
    const float* __restrict__ x,  const float* __restrict__ W,
    const float* __restrict__ Wq, const float* __restrict__ Wk)
{
    __shared__ float t[32][33];
    const int bid = blockIdx.x, tid = threadIdx.x;

    if (bid < 8192) {
        const int tx = tid & 31, ty = tid >> 5;
        const int c0 = (bid & 31) * 32;
        const int n0 = ((bid >> 5) & 7) * 32;
        const int b  = bid >> 8;
#pragma unroll
        for (int r = 0; r < 4; r++) {
            int row = ty + r * 8;
            size_t off = ((size_t)b * CC + c0 + row) * NSEQ + n0 + tx;
            float v = x[off];
            t[row][tx] = v;
            __nv_bfloat16 h, l; split_bf16(v, h, l);
            g_x_hi[off] = h;
            g_x_lo[off] = l;
        }
        __syncthreads();
#pragma unroll
        for (int r = 0; r < 4; r++) {
            int nrow = ty + r * 8;
            g_xT_hi[((size_t)b * NSEQ + n0 + nrow) * CC + c0 + tx] =
                __float2bfloat16(t[tx][nrow]);
        }
    } else if (bid < 9216) {
        size_t i = (size_t)(bid - 8192) * 256 + tid;
        float4 v = ((const float4*)W)[i];
        __nv_bfloat162* hp = (__nv_bfloat162*)g_wv_hi;
        __nv_bfloat162 a; a.x = __float2bfloat16(v.x); a.y = __float2bfloat16(v.y);
        __nv_bfloat162 bq; bq.x = __float2bfloat16(v.z); bq.y = __float2bfloat16(v.w);
        hp[i * 2] = a; hp[i * 2 + 1] = bq;
    } else {
        int r = bid - 9216;
        const float* src = (r < 64) ? (Wq + (size_t)r * NSEQ)
                                    : (Wk + (size_t)(r - 64) * NSEQ);
        float v = src[tid];
        __nv_bfloat16 h, l; split_bf16(v, h, l);
        g_wqk_hi[r * NSEQ + tid] = h;
        g_wqk_lo[r * NSEQ + tid] = l;
    }
}

// =====================================================================
// qk_mma2 (unchanged)
// =====================================================================
__global__ void __launch_bounds__(128, 2) qk_mma2(
    const float* __restrict__ g1, const float* __restrict__ b1,
    const float* __restrict__ m1, const float* __restrict__ v1,
    const float* __restrict__ g2, const float* __restrict__ b2,
    const float* __restrict__ m2, const float* __restrict__ v2)
{
    constexpr int STAGE = 49152;
    constexpr int BOFF  = 16384;

    extern __shared__ __align__(1024) char smem[];
    const u32 sbase = smem_u32(smem);
    const int tid = threadIdx.x;
    const int b   = blockIdx.z;
    const int n0  = blockIdx.x * 128;
    const int m0  = blockIdx.y * 64;

    const __nv_bfloat16* A_hi = g_wqk_hi;
    const __nv_bfloat16* A_lo = g_wqk_lo;
    const __nv_bfloat16* B_hi = g_x_hi + (size_t)b * CC * NSEQ;
    const __nv_bfloat16* B_lo = g_x_lo + (size_t)b * CC * NSEQ;

    auto load_slab = [&](int k0, int buf) {
        const u32 sb = sbase + buf * STAGE;
#pragma unroll
        for (int i = 0; i < 4; i++) {
            int idx = tid + i * 128;
            int row = idx >> 3, c = idx & 7;
            u32 dst = sb + row * 128 + ((c ^ (row & 7)) << 4);
            cp16(dst,        A_hi + (size_t)(m0 + row) * NSEQ + k0 + c * 8);
            cp16(dst + 8192, A_lo + (size_t)(m0 + row) * NSEQ + k0 + c * 8);
        }
#pragma unroll
        for (int i = 0; i < 8; i++) {
            int idx = tid + i * 128;
            int row = idx >> 3, c = idx & 7;
            u32 dst = sb + BOFF + row * 128 + ((c ^ (row & 7)) << 4);
            cp16(dst,         B_hi + (size_t)(n0 + row) * NSEQ + k0 + c * 8);
            cp16(dst + 16384, B_lo + (size_t)(n0 + row) * NSEQ + k0 + c * 8);
        }
        cp_commit();
    };

    const int lane = tid & 31;
    const int lr   = lane & 7;
    const int sub  = lane >> 3;
    const int warp = tid >> 5;
    const int wm   = warp >> 1, wn = warp & 1;

    const int a_row = wm * 32 + lr + (sub & 1) * 8;
    const int a_cad = sub >> 1;
    const int b_row = wn * 64 + lr + (sub >> 1) * 8;
    const int b_cad = sub & 1;

    float acc[2][8][4];
#pragma unroll
    for (int i = 0; i < 2; i++)
#pragma unroll
        for (int j = 0; j < 8; j++)
#pragma unroll
            for (int e = 0; e < 4; e++) acc[i][j][e] = 0.f;

    load_slab(0, 0);

    for (int s = 0; s < 4; s++) {
        if (s + 1 < 4) { load_slab((s + 1) * 64, (s + 1) & 1); cp_wait1(); }
        else           { cp_wait0(); }
        __syncthreads();

        const u32 sb = sbase + (s & 1) * STAGE;
#pragma unroll
        for (int kk = 0; kk < 4; kk++) {
            u32 bh[4][4], bl[4][4];
#pragma unroll
            for (int np = 0; np < 4; np++) {
                u32 badr = sb + BOFF + (b_row + np * 16) * 128
                         + (((kk * 2 + b_cad) ^ lr) << 4);
                ldsm4(badr,         bh[np][0], bh[np][1], bh[np][2], bh[np][3]);
                ldsm4(badr + 16384, bl[np][0], bl[np][1], bl[np][2], bl[np][3]);
            }
#pragma unroll
            for (int mt = 0; mt < 2; mt++) {
                u32 ah[4], al[4];
                u32 aadr = sb + (a_row + mt * 16) * 128
                         + (((kk * 2 + a_cad) ^ lr) << 4);
                ldsm4(aadr,        ah[0], ah[1], ah[2], ah[3]);
                ldsm4(aadr + 8192, al[0], al[1], al[2], al[3]);
#pragma unroll
                for (int np = 0; np < 4; np++) {
                    mma_bf16(acc[mt][2 * np],     ah, bh[np][0], bh[np][1]);
                    mma_bf16(acc[mt][2 * np + 1], ah, bh[np][2], bh[np][3]);
                    mma_bf16(acc[mt][2 * np],     al, bh[np][0], bh[np][1]);
                    mma_bf16(acc[mt][2 * np + 1], al, bh[np][2], bh[np][3]);
                    mma_bf16(acc[mt][2 * np],     ah, bl[np][0], bl[np][1]);
                    mma_bf16(acc[mt][2 * np + 1], ah, bl[np][2], bl[np][3]);
                }
            }
        }
        __syncthreads();
    }

    const bool is_q = (m0 == 0);
    float sc[2][2], bs[2][2];
#pragma unroll
    for (int mt = 0; mt < 2; mt++)
#pragma unroll
        for (int h = 0; h < 2; h++) {
            int o = wm * 32 + mt * 16 + (lane >> 2) + h * 8;
            float g, be, mn, vr;
            if (is_q) { g = g1[o]; be = b1[o]; mn = m1[o]; vr = v1[o]; }
            else      { g = g2[o]; be = b2[o]; mn = m2[o]; vr = v2[o]; }
            float s = g * rsqrtf(vr + EPS_BN);
            sc[mt][h] = s;
            bs[mt][h] = be - mn * s;
        }

    __nv_bfloat16* Th = (__nv_bfloat16*)smem;
    __nv_bfloat16* Tl = (__nv_bfloat16*)(smem + 18432);
    const int mloc = wm * 32 + (lane >> 2);
    const int nbas = wn * 64 + (lane & 3) * 2;
#pragma unroll
    for (int mt = 0; mt < 2; mt++)
#pragma unroll
        for (int jj = 0; jj < 8; jj++)
#pragma unroll
            for (int e = 0; e < 4; e++) {
                int h = e >> 1, col = e & 1;
                float val = fmaxf(acc[mt][jj][e] * sc[mt][h] + bs[mt][h], 0.f);
                int off = (nbas + jj * 8 + col) * 72 + mloc + mt * 16 + h * 8;
                __nv_bfloat16 hi, lo; split_bf16(val, hi, lo);
                Th[off] = hi;
                Tl[off] = lo;
            }
    __syncthreads();

    __nv_bfloat16* Dh = is_q ? g_qT_hi : g_kT_hi;
    __nv_bfloat16* Dl = is_q ? g_qT_lo : g_kT_lo;
#pragma unroll
    for (int i = 0; i < 8; i++) {
        int idx = tid + i * 128;
        int c = idx >> 3, ch = idx & 7;
        size_t dst = ((size_t)b * CC + n0 + c) * DQ + ch * 8;
        *(uint4*)&Dh[dst] = *(uint4*)&Th[c * 72 + ch * 8];
        *(uint4*)&Dl[dst] = *(uint4*)&Tl[c * 72 + ch * 8];
    }
}

// =====================================================================
// v_mma (unchanged)
// =====================================================================
__global__ void __launch_bounds__(128, 3) v_mma(
    const float* __restrict__ gA, const float* __restrict__ bA,
    const float* __restrict__ mA, const float* __restrict__ vA)
{
    constexpr int STAGE = 24576;
    constexpr int BOFF  = 8192;

    extern __shared__ __align__(1024) char smem[];
    const u32 sbase = smem_u32(smem);
    const int tid  = threadIdx.x;
    const int lane = tid & 31;
    const int lr   = lane & 7;
    const int sub  = lane >> 3;
    const int warp = tid >> 5;
    const int wm   = warp >> 1, wn = warp & 1;
    const int b    = blockIdx.z;
    const int n0   = blockIdx.x * 128;
    const int m0   = blockIdx.y * 64;

    const __nv_bfloat16* A_hi = g_wv_hi;
    const __nv_bfloat16* B_hi = g_xT_hi + (size_t)b * NSEQ * CC;

    auto load_slab = [&](int k0, int buf) {
        const u32 sb = sbase + buf * STAGE;
#pragma unroll
        for (int i = 0; i < 4; i++) {
            int idx = tid + i * 128;
            int row = idx >> 3, c = idx & 7;
            u32 dst = sb + row * 128 + ((c ^ (row & 7)) << 4);
            cp16(dst, A_hi + (size_t)(m0 + row) * CC + k0 + c * 8);
        }
#pragma unroll
        for (int i = 0; i < 8; i++) {
            int idx = tid + i * 128;
            int row = idx >> 3, c = idx & 7;
            u32 dst = sb + BOFF + row * 128 + ((c ^ (row & 7)) << 4);
            cp16(dst, B_hi + (size_t)(n0 + row) * CC + k0 + c * 8);
        }
        cp_commit();
    };

    const int a_row = wm * 32 + lr + (sub & 1) * 8;
    const int a_cad = sub >> 1;
    const int b_row = wn * 64 + lr + (sub >> 1) * 8;
    const int b_cad = sub & 1;

    float acc[2][8][4];
#pragma unroll
    for (int i = 0; i < 2; i++)
#pragma unroll
        for (int j = 0; j < 8; j++)
#pragma unroll
            for (int e = 0; e < 4; e++) acc[i][j][e] = 0.f;

    load_slab(0, 0);

    for (int s = 0; s < 16; s++) {
        if (s + 1 < 16) { load_slab((s + 1) * 64, (s + 1) & 1); cp_wait1(); }
        else            { cp_wait0(); }
        __syncthreads();

        const u32 sb = sbase + (s & 1) * STAGE;
#pragma unroll
        for (int kk = 0; kk < 4; kk++) {
            u32 bh[4][4];
#pragma unroll
            for (int np = 0; np < 4; np++) {
                u32 badr = sb + BOFF + (b_row + np * 16) * 128
                         + (((kk * 2 + b_cad) ^ lr) << 4);
                ldsm4(badr, bh[np][0], bh[np][1], bh[np][2], bh[np][3]);
            }
#pragma unroll
            for (int mt = 0; mt < 2; mt++) {
                u32 ah[4];
                u32 aadr = sb + (a_row + mt * 16) * 128
                         + (((kk * 2 + a_cad) ^ lr) << 4);
                ldsm4(aadr, ah[0], ah[1], ah[2], ah[3]);
#pragma unroll
                for (int np = 0; np < 4; np++) {
                    mma_bf16(acc[mt][2 * np],     ah, bh[np][0], bh[np][1]);
                    mma_bf16(acc[mt][2 * np + 1], ah, bh[np][2], bh[np][3]);
                }
            }
        }
        __syncthreads();
    }

    float sc[2][2], bs[2][2];
#pragma unroll
    for (int mt = 0; mt < 2; mt++)
#pragma unroll
        for (int h = 0; h < 2; h++) {
            int m = m0 + wm * 32 + mt * 16 + (lane >> 2) + h * 8;
            float s = gA[m] * rsqrtf(vA[m] + EPS_BN);
            sc[mt][h] = s;
            bs[mt][h] = bA[m] - mA[m] * s;
        }

    __nv_bfloat16* Th = (__nv_bfloat16*)smem;   // [128 n][72 m]
    const int mloc = wm * 32 + (lane >> 2);
    const int nbas = wn * 64 + (lane & 3) * 2;
#pragma unroll
    for (int mt = 0; mt < 2; mt++)
#pragma unroll
        for (int jj = 0; jj < 8; jj++)
#pragma unroll
            for (int e = 0; e < 4; e++) {
                int h = e >> 1, col = e & 1;
                float val = fmaxf(acc[mt][jj][e] * sc[mt][h] + bs[mt][h], 0.f);
                int off = (nbas + jj * 8 + col) * 72 + mloc + mt * 16 + h * 8;
                Th[off] = __float2bfloat16(val);
            }
    __syncthreads();

#pragma unroll
    for (int i = 0; i < 8; i++) {
        int idx = tid + i * 128;
        int n = idx >> 3, ch = idx & 7;
        uint4 hv = *(uint4*)&Th[n * 72 + ch * 8];
        size_t dst = ((size_t)b * NSEQ + n0 + n) * CC + m0 + ch * 8;
        *(uint4*)&g_vT_hi[dst] = hv;
    }
}

// =====================================================================
// sim_exp: batch-chunked (b = b0 + blockIdx.z). grid (8, 16, 16)
// =====================================================================
__global__ void __launch_bounds__(128, 3) sim_exp(int b0)
{
    extern __shared__ __align__(1024) char smem[];
    const u32 sbase = smem_u32(smem);
    const int tid  = threadIdx.x;
    const int lane = tid & 31;
    const int lr   = lane & 7;
    const int sub  = lane >> 3;
    const int warp = tid >> 5;
    const int wm   = warp >> 1, wn = warp & 1;
    const int b    = b0 + blockIdx.z;
    const int dt   = blockIdx.x;
    const int c0   = blockIdx.y * 64;
    const int d0   = dt * 128;

    const __nv_bfloat16* Ah = g_kT_hi + ((size_t)b * CC + c0) * DQ;
    const __nv_bfloat16* Al = g_kT_lo + ((size_t)b * CC + c0) * DQ;
    const __nv_bfloat16* Bh = g_qT_hi + ((size_t)b * CC + d0) * DQ;
    const __nv_bfloat16* Bl = g_qT_lo + ((size_t)b * CC + d0) * DQ;

#pragma unroll
    for (int i = 0; i < 4; i++) {
        int idx = tid + i * 128;
        int row = idx >> 3, c = idx & 7;
        u32 dst = sbase + row * 128 + ((c ^ (row & 7)) << 4);
        cp16(dst,        Ah + (size_t)row * DQ + c * 8);
        cp16(dst + 8192, Al + (size_t)row * DQ + c * 8);
    }
#pragma unroll
    for (int i = 0; i < 8; i++) {
        int idx = tid + i * 128;
        int row = idx >> 3, c = idx & 7;
        u32 dst = sbase + 16384 + row * 128 + ((c ^ (row & 7)) << 4);
        cp16(dst,         Bh + (size_t)row * DQ + c * 8);
        cp16(dst + 16384, Bl + (size_t)row * DQ + c * 8);
    }
    cp_commit();
    cp_wait0();
    __syncthreads();

    const int a_row = wm * 32 + lr + (sub & 1) * 8;
    const int a_cad = sub >> 1;
    const int b_row = wn * 64 + lr + (sub >> 1) * 8;
    const int b_cad = sub & 1;

    float acc[2][8][4];
#pragma unroll
    for (int i = 0; i < 2; i++)
#pragma unroll
        for (int j = 0; j < 8; j++)
#pragma unroll
            for (int e = 0; e < 4; e++) acc[i][j][e] = 0.f;

#pragma unroll
    for (int kk = 0; kk < 4; kk++) {
        u32 bh[4][4], bl[4][4];
#pragma unroll
        for (int np = 0; np < 4; np++) {
            u32 badr = sbase + 16384 + (b_row + np * 16) * 128
                     + (((kk * 2 + b_cad) ^ lr) << 4);
            ldsm4(badr,         bh[np][0], bh[np][1], bh[np][2], bh[np][3]);
            ldsm4(badr + 16384, bl[np][0], bl[np][1], bl[np][2], bl[np][3]);
        }
#pragma unroll
        for (int mt = 0; mt < 2; mt++) {
            u32 ah[4], al[4];
            u32 aadr = sbase + (a_row + mt * 16) * 128
                     + (((kk * 2 + a_cad) ^ lr) << 4);
            ldsm4(aadr,        ah[0], ah[1], ah[2], ah[3]);
            ldsm4(aadr + 8192, al[0], al[1], al[2], al[3]);
#pragma unroll
            for (int np = 0; np < 4; np++) {
                mma_bf16(acc[mt][2 * np],     ah, bh[np][0], bh[np][1]);
                mma_bf16(acc[mt][2 * np + 1], ah, bh[np][2], bh[np][3]);
                mma_bf16(acc[mt][2 * np],     al, bh[np][0], bh[np][1]);
                mma_bf16(acc[mt][2 * np + 1], al, bh[np][2], bh[np][3]);
                mma_bf16(acc[mt][2 * np],     ah, bl[np][0], bl[np][1]);
                mma_bf16(acc[mt][2 * np + 1], ah, bl[np][2], bl[np][3]);
            }
        }
    }
    __syncthreads();

    __nv_bfloat16* st   = (__nv_bfloat16*)smem;        // [64][144]
    float*         sums = (float*)(smem + 18432);      // [64][2]
    const int grp = lane >> 2, qt = lane & 3;

#pragma unroll
    for (int mt = 0; mt < 2; mt++)
#pragma unroll
        for (int h = 0; h < 2; h++) {
            int r = wm * 32 + mt * 16 + grp + h * 8;
            float s = 0.f;
#pragma unroll
            for (int jj = 0; jj < 8; jj++) {
                float e0 = __expf(-acc[mt][jj][2 * h]);
                float e1 = __expf(-acc[mt][jj][2 * h + 1]);
                s += e0 + e1;
                __nv_bfloat162 p;
                p.x = __float2bfloat16(e0);
                p.y = __float2bfloat16(e1);
                *(__nv_bfloat162*)&st[r * 144 + wn * 64 + jj * 8 + qt * 2] = p;
            }
            s += __shfl_xor_sync(~0u, s, 1);
            s += __shfl_xor_sync(~0u, s, 2);
            if (qt == 0) sums[r * 2 + wn] = s;
        }
    __syncthreads();

    if (tid < 64) {
        float S = sums[tid * 2] + sums[tid * 2 + 1];
        g_psum[((size_t)b * CC + c0 + tid) * 8 + dt] = S;
    }

#pragma unroll
    for (int i = 0; i < 8; i++) {
        int idx = tid + i * 128;
        int row = idx >> 4, ch = idx & 15;
        uint4 v = *(uint4*)&st[row * 144 + ch * 8];
        *(uint4*)&g_aff_hi[((size_t)b * CC + c0 + row) * CC + d0 + ch * 8] = v;
    }
}

// =====================================================================
// out_mma: batch-chunked (b = b0 + blockIdx.z). grid (2, 16, 16)
// =====================================================================
__global__ void __launch_bounds__(128, 4) out_mma(
    float* __restrict__ Cout, const float* __restrict__ xres,
    const float* __restrict__ alpha, int b0)
{
    constexpr int STAGE = 24576;
    constexpr int BOFF  = 8192;

    extern __shared__ __align__(1024) char smem[];
    const u32 sbase = smem_u32(smem);
    const int tid = threadIdx.x;
    const int b   = b0 + blockIdx.z;
    const int n0  = blockIdx.x * 128;
    const int m0  = blockIdx.y * 64;

    const __nv_bfloat16* A_hi = g_aff_hi + (size_t)b * CC * CC;
    const __nv_bfloat16* B_hi = g_vT_hi + (size_t)b * NSEQ * CC;

    auto load_slab = [&](int k0, int buf) {
        const u32 sb = sbase + buf * STAGE;
#pragma unroll
        for (int i = 0; i < 4; i++) {
            int idx = tid + i * 128;
            int row = idx >> 3, c = idx & 7;
            u32 dst = sb + row * 128 + ((c ^ (row & 7)) << 4);
            cp16(dst, A_hi + (size_t)(m0 + row) * CC + k0 + c * 8);
        }
#pragma unroll
        for (int i = 0; i < 8; i++) {
            int idx = tid + i * 128;
            int row = idx >> 3, c = idx & 7;
            u32 dst = sb + BOFF + row * 128 + ((c ^ (row & 7)) << 4);
            cp16(dst, B_hi + (size_t)(n0 + row) * CC + k0 + c * 8);
        }
        cp_commit();
    };

    const int lane = tid & 31;
    const int lr   = lane & 7;
    const int sub  = lane >> 3;
    const int warp = tid >> 5;
    const int wm   = warp >> 1, wn = warp & 1;

    const int a_row = wm * 32 + lr + (sub & 1) * 8;
    const int a_cad = sub >> 1;
    const int b_row = wn * 64 + lr + (sub >> 1) * 8;
    const int b_cad = sub & 1;

    float acc[2][8][4];
#pragma unroll
    for (int i = 0; i < 2; i++)
#pragma unroll
        for (int j = 0; j < 8; j++)
#pragma unroll
            for (int e = 0; e < 4; e++) acc[i][j][e] = 0.f;

    load_slab(0, 0);

    for (int s = 0; s < 16; s++) {
        if (s + 1 < 16) { load_slab((s + 1) * 64, (s + 1) & 1); cp_wait1(); }
        else            { cp_wait0(); }
        __syncthreads();

        const u32 sb = sbase + (s & 1) * STAGE;
#pragma unroll
        for (int kk = 0; kk < 4; kk++) {
            u32 bh[4][4];
#pragma unroll
            for (int np = 0; np < 4; np++) {
                u32 badr = sb + BOFF + (b_row + np * 16) * 128
                         + (((kk * 2 + b_cad) ^ lr) << 4);
                ldsm4(badr, bh[np][0], bh[np][1], bh[np][2], bh[np][3]);
            }
#pragma unroll
            for (int mt = 0; mt < 2; mt++) {
                u32 ah[4];
                u32 aadr = sb + (a_row + mt * 16) * 128
                         + (((kk * 2 + a_cad) ^ lr) << 4);
                ldsm4(aadr, ah[0], ah[1], ah[2], ah[3]);
#pragma unroll
                for (int np = 0; np < 4; np++) {
                    mma_bf16(acc[mt][2 * np],     ah, bh[np][0], bh[np][1]);
                    mma_bf16(acc[mt][2 * np + 1], ah, bh[np][2], bh[np][3]);
                }
            }
        }
        __syncthreads();
    }

    const float al_ = alpha[0];
    float scl[2][2];
#pragma unroll
    for (int mt = 0; mt < 2; mt++)
#pragma unroll
        for (int h = 0; h < 2; h++) {
            int m = m0 + wm * 32 + mt * 16 + (lane >> 2) + h * 8;
            const float4* p = (const float4*)&g_psum[((size_t)b * CC + m) * 8];
            float4 u = p[0], v = p[1];
            float S = (u.x + u.y) + (u.z + u.w) + (v.x + v.y) + (v.z + v.w);
            scl[mt][h] = al_ / S;
        }
#pragma unroll
    for (int mt = 0; mt < 2; mt++) {
        int m = m0 + wm * 32 + mt * 16 + (lane >> 2);
#pragma unroll
        for (int jj = 0; jj < 8; jj++) {
            int nn = n0 + wn * 64 + (lane & 3) * 2 + jj * 8;
            size_t b0i = ((size_t)b * CC + m) * NSEQ + nn;
            size_t b1i = b0i + 8 * NSEQ;
            float2 x0 = *(const float2*)&xres[b0i];
            float2 x1 = *(const float2*)&xres[b1i];
            float2 o0, o1;
            o0.x = scl[mt][0] * acc[mt][jj][0] + x0.x;
            o0.y = scl[mt][0] * acc[mt][jj][1] + x0.y;
            o1.x = scl[mt][1] * acc[mt][jj][2] + x1.x;
            o1.y = scl[mt][1] * acc[mt][jj][3] + x1.y;
            *(float2*)&Cout[b0i] = o0;
            *(float2*)&Cout[b1i] = o1;
        }
    }
}

// =====================================================================
extern "C" void kernel_launch(void* const* d_in, const int* in_sizes, int n_in,
                              void* d_out, int out_size)
{
    const float* x    = (const float*)d_in[0];
    const float* Wq   = (const float*)d_in[1];
    const float* Wk   = (const float*)d_in[2];
    const float* Wv   = (const float*)d_in[3];
    const float* bn1g = (const float*)d_in[4];
    const float* bn1b = (const float*)d_in[5];
    const float* bn1m = (const float*)d_in[6];
    const float* bn1v = (const float*)d_in[7];
    const float* bn2g = (const float*)d_in[8];
    const float* bn2b = (const float*)d_in[9];
    const float* bn2m = (const float*)d_in[10];
    const float* bn2v = (const float*)d_in[11];
    const float* bn3g = (const float*)d_in[12];
    const float* bn3b = (const float*)d_in[13];
    const float* bn3m = (const float*)d_in[14];
    const float* bn3v = (const float*)d_in[15];
    const float* alpha= (const float*)d_in[16];
    float* out = (float*)d_out;

    static cudaStream_t s1 = nullptr;
    static cudaEvent_t  ec = nullptr, eA = nullptr, eB = nullptr, eo = nullptr;
    if (s1 == nullptr) {
        cudaStreamCreateWithFlags(&s1, cudaStreamNonBlocking);
        cudaEventCreateWithFlags(&ec, cudaEventDisableTiming);
        cudaEventCreateWithFlags(&eA, cudaEventDisableTiming);
        cudaEventCreateWithFlags(&eB, cudaEventDisableTiming);
        cudaEventCreateWithFlags(&eo, cudaEventDisableTiming);
    }

    cudaFuncSetAttribute(qk_mma2, cudaFuncAttributeMaxDynamicSharedMemorySize, 98304);
    cudaFuncSetAttribute(v_mma,   cudaFuncAttributeMaxDynamicSharedMemorySize, 49152);
    cudaFuncSetAttribute(sim_exp, cudaFuncAttributeMaxDynamicSharedMemorySize, 49152);
    cudaFuncSetAttribute(out_mma, cudaFuncAttributeMaxDynamicSharedMemorySize, 49152);

    // main stream: converts
    convert_all<<<9344, 256>>>(x, Wv, Wq, Wk);

    // fork: v on side stream (independent of qk/sim)
    cudaEventRecord(ec, 0);
    cudaStreamWaitEvent(s1, ec, 0);
    v_mma<<<dim3(2, 16, BB), 128, 49152, s1>>>(bn3g, bn3b, bn3m, bn3v);

    // main stream: qk, then sim in two batch halves
    qk_mma2<<<dim3(CC / 128, 2, BB), 128, 98304>>>(
        bn1g, bn1b, bn1m, bn1v, bn2g, bn2b, bn2m, bn2v);

    sim_exp<<<dim3(8, 16, 16), 128, 49152>>>(0);        // batches 0..15
    cudaEventRecord(eA, 0);
    sim_exp<<<dim3(8, 16, 16), 128, 49152>>>(16);       // batches 16..31
    cudaEventRecord(eB, 0);

    // side stream: out_A after {v (stream order), sim_A}; overlaps sim_B
    cudaStreamWaitEvent(s1, eA, 0);
    out_mma<<<dim3(2, 16, 16), 128, 49152, s1>>>(out, x, alpha, 0);
    cudaStreamWaitEvent(s1, eB, 0);
    out_mma<<<dim3(2, 16, 16), 128, 49152, s1>>>(out, x, alpha, 16);

    // join side stream back to capture origin
    cudaEventRecord(eo, s1);
    cudaStreamWaitEvent(0, eo, 0);
}

// round 16
// speedup vs baseline: 1.1231x; 1.1231x over previous
#include <cuda_runtime.h>
#include <cuda_bf16.h>
#include <cstdint>

#define BB   32
#define CC   1024
#define NSEQ 256
#define DQ   64
#define EPS_BN 1e-5f

typedef unsigned long long u64;
typedef unsigned int u32;

// ---------------- scratch (static device memory) ----------------
__device__ __nv_bfloat16 g_x_hi[(size_t)BB * CC * NSEQ];
__device__ __nv_bfloat16 g_x_lo[(size_t)BB * CC * NSEQ];
__device__ __nv_bfloat16 g_xT_hi[(size_t)BB * NSEQ * CC];
__device__ __nv_bfloat16 g_wv_hi[(size_t)CC * CC];
__device__ __nv_bfloat16 g_wqk_hi[128 * NSEQ];
__device__ __nv_bfloat16 g_wqk_lo[128 * NSEQ];
__device__ __nv_bfloat16 g_qT_hi[(size_t)BB * CC * DQ];
__device__ __nv_bfloat16 g_qT_lo[(size_t)BB * CC * DQ];
__device__ __nv_bfloat16 g_kT_hi[(size_t)BB * CC * DQ];
__device__ __nv_bfloat16 g_kT_lo[(size_t)BB * CC * DQ];
__device__ __nv_bfloat16 g_aff_hi[(size_t)BB * CC * CC];    // UNNORMALIZED exp
__device__ float         g_psum[(size_t)BB * CC * 8];
__device__ __nv_bfloat16 g_vT_hi[(size_t)BB * NSEQ * CC];

// ---------------- helpers ----------------
__device__ __forceinline__ u32 smem_u32(const void* p) {
    u32 a;
    asm("{ .reg .u64 t; cvta.to.shared.u64 t, %1; cvt.u32.u64 %0, t; }"
        : "=r"(a) : "l"(p));
    return a;
}
__device__ __forceinline__ void split_bf16(float v, __nv_bfloat16& h, __nv_bfloat16& l) {
    h = __float2bfloat16(v);
    l = __float2bfloat16(v - __bfloat162float(h));
}
__device__ __forceinline__ void cp16(u32 dst, const void* src) {
    asm volatile("cp.async.cg.shared.global [%0], [%1], 16;" :: "r"(dst), "l"(src));
}
__device__ __forceinline__ void cp_commit() {
    asm volatile("cp.async.commit_group;" ::: "memory");
}
__device__ __forceinline__ void cp_wait1() {
    asm volatile("cp.async.wait_group 1;" ::: "memory");
}
__device__ __forceinline__ void cp_wait0() {
    asm volatile("cp.async.wait_group 0;" ::: "memory");
}
__device__ __forceinline__ void ldsm4(u32 addr, u32& r0, u32& r1, u32& r2, u32& r3) {
    asm volatile("ldmatrix.sync.aligned.m8n8.x4.shared.b16 {%0,%1,%2,%3}, [%4];"
                 : "=r"(r0), "=r"(r1), "=r"(r2), "=r"(r3) : "r"(addr));
}
__device__ __forceinline__ void mma_bf16(float* c, const u32* a, u32 b0, u32 b1) {
    asm volatile(
        "mma.sync.aligned.m16n8k16.row.col.f32.bf16.bf16.f32 "
        "{%0,%1,%2,%3}, {%4,%5,%6,%7}, {%8,%9}, {%0,%1,%2,%3};"
        : "+f"(c[0]), "+f"(c[1]), "+f"(c[2]), "+f"(c[3])
        : "r"(a[0]), "r"(a[1]), "r"(a[2]), "r"(a[3]), "r"(b0), "r"(b1));
}

// =====================================================================
// convert_all (unchanged)
// =====================================================================
__global__ __launch_bounds__(256) void convert_all(
    const float* __restrict__ x,  const float* __restrict__ W,
    const float* __restrict__ Wq, const float* __restrict__ Wk)
{
    __shared__ float t[32][33];
    const int bid = blockIdx.x, tid = threadIdx.x;

    if (bid < 8192) {
        const int tx = tid & 31, ty = tid >> 5;
        const int c0 = (bid & 31) * 32;
        const int n0 = ((bid >> 5) & 7) * 32;
        const int b  = bid >> 8;
#pragma unroll
        for (int r = 0; r < 4; r++) {
            int row = ty + r * 8;
            size_t off = ((size_t)b * CC + c0 + row) * NSEQ + n0 + tx;
            float v = x[off];
            t[row][tx] = v;
            __nv_bfloat16 h, l; split_bf16(v, h, l);
            g_x_hi[off] = h;
            g_x_lo[off] = l;
        }
        __syncthreads();
#pragma unroll
        for (int r = 0; r < 4; r++) {
            int nrow = ty + r * 8;
            g_xT_hi[((size_t)b * NSEQ + n0 + nrow) * CC + c0 + tx] =
                __float2bfloat16(t[tx][nrow]);
        }
    } else if (bid < 9216) {
        size_t i = (size_t)(bid - 8192) * 256 + tid;
        float4 v = ((const float4*)W)[i];
        __nv_bfloat162* hp = (__nv_bfloat162*)g_wv_hi;
        __nv_bfloat162 a; a.x = __float2bfloat16(v.x); a.y = __float2bfloat16(v.y);
        __nv_bfloat162 bq; bq.x = __float2bfloat16(v.z); bq.y = __float2bfloat16(v.w);
        hp[i * 2] = a; hp[i * 2 + 1] = bq;
    } else {
        int r = bid - 9216;
        const float* src = (r < 64) ? (Wq + (size_t)r * NSEQ)
                                    : (Wk + (size_t)(r - 64) * NSEQ);
        float v = src[tid];
        __nv_bfloat16 h, l; split_bf16(v, h, l);
        g_wqk_hi[r * NSEQ + tid] = h;
        g_wqk_lo[r * NSEQ + tid] = l;
    }
}

// =====================================================================
// qk_mma2 (unchanged)
// =====================================================================
__global__ void __launch_bounds__(128, 2) qk_mma2(
    const float* __restrict__ g1, const float* __restrict__ b1,
    const float* __restrict__ m1, const float* __restrict__ v1,
    const float* __restrict__ g2, const float* __restrict__ b2,
    const float* __restrict__ m2, const float* __restrict__ v2)
{
    constexpr int STAGE = 49152;
    constexpr int BOFF  = 16384;

    extern __shared__ __align__(1024) char smem[];
    const u32 sbase = smem_u32(smem);
    const int tid = threadIdx.x;
    const int b   = blockIdx.z;
    const int n0  = blockIdx.x * 128;
    const int m0  = blockIdx.y * 64;

    const __nv_bfloat16* A_hi = g_wqk_hi;
    const __nv_bfloat16* A_lo = g_wqk_lo;
    const __nv_bfloat16* B_hi = g_x_hi + (size_t)b * CC * NSEQ;
    const __nv_bfloat16* B_lo = g_x_lo + (size_t)b * CC * NSEQ;

    auto load_slab = [&](int k0, int buf) {
        const u32 sb = sbase + buf * STAGE;
#pragma unroll
        for (int i = 0; i < 4; i++) {
            int idx = tid + i * 128;
            int row = idx >> 3, c = idx & 7;
            u32 dst = sb + row * 128 + ((c ^ (row & 7)) << 4);
            cp16(dst,        A_hi + (size_t)(m0 + row) * NSEQ + k0 + c * 8);
            cp16(dst + 8192, A_lo + (size_t)(m0 + row) * NSEQ + k0 + c * 8);
        }
#pragma unroll
        for (int i = 0; i < 8; i++) {
            int idx = tid + i * 128;
            int row = idx >> 3, c = idx & 7;
            u32 dst = sb + BOFF + row * 128 + ((c ^ (row & 7)) << 4);
            cp16(dst,         B_hi + (size_t)(n0 + row) * NSEQ + k0 + c * 8);
            cp16(dst + 16384, B_lo + (size_t)(n0 + row) * NSEQ + k0 + c * 8);
        }
        cp_commit();
    };

    const int lane = tid & 31;
    const int lr   = lane & 7;
    const int sub  = lane >> 3;
    const int warp = tid >> 5;
    const int wm   = warp >> 1, wn = warp & 1;

    const int a_row = wm * 32 + lr + (sub & 1) * 8;
    const int a_cad = sub >> 1;
    const int b_row = wn * 64 + lr + (sub >> 1) * 8;
    const int b_cad = sub & 1;

    float acc[2][8][4];
#pragma unroll
    for (int i = 0; i < 2; i++)
#pragma unroll
        for (int j = 0; j < 8; j++)
#pragma unroll
            for (int e = 0; e < 4; e++) acc[i][j][e] = 0.f;

    load_slab(0, 0);

    for (int s = 0; s < 4; s++) {
        if (s + 1 < 4) { load_slab((s + 1) * 64, (s + 1) & 1); cp_wait1(); }
        else           { cp_wait0(); }
        __syncthreads();

        const u32 sb = sbase + (s & 1) * STAGE;
#pragma unroll
        for (int kk = 0; kk < 4; kk++) {
            u32 bh[4][4], bl[4][4];
#pragma unroll
            for (int np = 0; np < 4; np++) {
                u32 badr = sb + BOFF + (b_row + np * 16) * 128
                         + (((kk * 2 + b_cad) ^ lr) << 4);
                ldsm4(badr,         bh[np][0], bh[np][1], bh[np][2], bh[np][3]);
                ldsm4(badr + 16384, bl[np][0], bl[np][1], bl[np][2], bl[np][3]);
            }
#pragma unroll
            for (int mt = 0; mt < 2; mt++) {
                u32 ah[4], al[4];
                u32 aadr = sb + (a_row + mt * 16) * 128
                         + (((kk * 2 + a_cad) ^ lr) << 4);
                ldsm4(aadr,        ah[0], ah[1], ah[2], ah[3]);
                ldsm4(aadr + 8192, al[0], al[1], al[2], al[3]);
#pragma unroll
                for (int np = 0; np < 4; np++) {
                    mma_bf16(acc[mt][2 * np],     ah, bh[np][0], bh[np][1]);
                    mma_bf16(acc[mt][2 * np + 1], ah, bh[np][2], bh[np][3]);
                    mma_bf16(acc[mt][2 * np],     al, bh[np][0], bh[np][1]);
                    mma_bf16(acc[mt][2 * np + 1], al, bh[np][2], bh[np][3]);
                    mma_bf16(acc[mt][2 * np],     ah, bl[np][0], bl[np][1]);
                    mma_bf16(acc[mt][2 * np + 1], ah, bl[np][2], bl[np][3]);
                }
            }
        }
        __syncthreads();
    }

    const bool is_q = (m0 == 0);
    float sc[2][2], bs[2][2];
#pragma unroll
    for (int mt = 0; mt < 2; mt++)
#pragma unroll
        for (int h = 0; h < 2; h++) {
            int o = wm * 32 + mt * 16 + (lane >> 2) + h * 8;
            float g, be, mn, vr;
            if (is_q) { g = g1[o]; be = b1[o]; mn = m1[o]; vr = v1[o]; }
            else      { g = g2[o]; be = b2[o]; mn = m2[o]; vr = v2[o]; }
            float s = g * rsqrtf(vr + EPS_BN);
            sc[mt][h] = s;
            bs[mt][h] = be - mn * s;
        }

    __nv_bfloat16* Th = (__nv_bfloat16*)smem;
    __nv_bfloat16* Tl = (__nv_bfloat16*)(smem + 18432);
    const int mloc = wm * 32 + (lane >> 2);
    const int nbas = wn * 64 + (lane & 3) * 2;
#pragma unroll
    for (int mt = 0; mt < 2; mt++)
#pragma unroll
        for (int jj = 0; jj < 8; jj++)
#pragma unroll
            for (int e = 0; e < 4; e++) {
                int h = e >> 1, col = e & 1;
                float val = fmaxf(acc[mt][jj][e] * sc[mt][h] + bs[mt][h], 0.f);
                int off = (nbas + jj * 8 + col) * 72 + mloc + mt * 16 + h * 8;
                __nv_bfloat16 hi, lo; split_bf16(val, hi, lo);
                Th[off] = hi;
                Tl[off] = lo;
            }
    __syncthreads();

    __nv_bfloat16* Dh = is_q ? g_qT_hi : g_kT_hi;
    __nv_bfloat16* Dl = is_q ? g_qT_lo : g_kT_lo;
#pragma unroll
    for (int i = 0; i < 8; i++) {
        int idx = tid + i * 128;
        int c = idx >> 3, ch = idx & 7;
        size_t dst = ((size_t)b * CC + n0 + c) * DQ + ch * 8;
        *(uint4*)&Dh[dst] = *(uint4*)&Th[c * 72 + ch * 8];
        *(uint4*)&Dl[dst] = *(uint4*)&Tl[c * 72 + ch * 8];
    }
}

// =====================================================================
// v_mma (unchanged)
// =====================================================================
__global__ void __launch_bounds__(128, 3) v_mma(
    const float* __restrict__ gA, const float* __restrict__ bA,
    const float* __restrict__ mA, const float* __restrict__ vA)
{
    constexpr int STAGE = 24576;
    constexpr int BOFF  = 8192;

    extern __shared__ __align__(1024) char smem[];
    const u32 sbase = smem_u32(smem);
    const int tid  = threadIdx.x;
    const int lane = tid & 31;
    const int lr   = lane & 7;
    const int sub  = lane >> 3;
    const int warp = tid >> 5;
    const int wm   = warp >> 1, wn = warp & 1;
    const int b    = blockIdx.z;
    const int n0   = blockIdx.x * 128;
    const int m0   = blockIdx.y * 64;

    const __nv_bfloat16* A_hi = g_wv_hi;
    const __nv_bfloat16* B_hi = g_xT_hi + (size_t)b * NSEQ * CC;

    auto load_slab = [&](int k0, int buf) {
        const u32 sb = sbase + buf * STAGE;
#pragma unroll
        for (int i = 0; i < 4; i++) {
            int idx = tid + i * 128;
            int row = idx >> 3, c = idx & 7;
            u32 dst = sb + row * 128 + ((c ^ (row & 7)) << 4);
            cp16(dst, A_hi + (size_t)(m0 + row) * CC + k0 + c * 8);
        }
#pragma unroll
        for (int i = 0; i < 8; i++) {
            int idx = tid + i * 128;
            int row = idx >> 3, c = idx & 7;
            u32 dst = sb + BOFF + row * 128 + ((c ^ (row & 7)) << 4);
            cp16(dst, B_hi + (size_t)(n0 + row) * CC + k0 + c * 8);
        }
        cp_commit();
    };

    const int a_row = wm * 32 + lr + (sub & 1) * 8;
    const int a_cad = sub >> 1;
    const int b_row = wn * 64 + lr + (sub >> 1) * 8;
    const int b_cad = sub & 1;

    float acc[2][8][4];
#pragma unroll
    for (int i = 0; i < 2; i++)
#pragma unroll
        for (int j = 0; j < 8; j++)
#pragma unroll
            for (int e = 0; e < 4; e++) acc[i][j][e] = 0.f;

    load_slab(0, 0);

    for (int s = 0; s < 16; s++) {
        if (s + 1 < 16) { load_slab((s + 1) * 64, (s + 1) & 1); cp_wait1(); }
        else            { cp_wait0(); }
        __syncthreads();

        const u32 sb = sbase + (s & 1) * STAGE;
#pragma unroll
        for (int kk = 0; kk < 4; kk++) {
            u32 bh[4][4];
#pragma unroll
            for (int np = 0; np < 4; np++) {
                u32 badr = sb + BOFF + (b_row + np * 16) * 128
                         + (((kk * 2 + b_cad) ^ lr) << 4);
                ldsm4(badr, bh[np][0], bh[np][1], bh[np][2], bh[np][3]);
            }
#pragma unroll
            for (int mt = 0; mt < 2; mt++) {
                u32 ah[4];
                u32 aadr = sb + (a_row + mt * 16) * 128
                         + (((kk * 2 + a_cad) ^ lr) << 4);
                ldsm4(aadr, ah[0], ah[1], ah[2], ah[3]);
#pragma unroll
                for (int np = 0; np < 4; np++) {
                    mma_bf16(acc[mt][2 * np],     ah, bh[np][0], bh[np][1]);
                    mma_bf16(acc[mt][2 * np + 1], ah, bh[np][2], bh[np][3]);
                }
            }
        }
        __syncthreads();
    }

    float sc[2][2], bs[2][2];
#pragma unroll
    for (int mt = 0; mt < 2; mt++)
#pragma unroll
        for (int h = 0; h < 2; h++) {
            int m = m0 + wm * 32 + mt * 16 + (lane >> 2) + h * 8;
            float s = gA[m] * rsqrtf(vA[m] + EPS_BN);
            sc[mt][h] = s;
            bs[mt][h] = bA[m] - mA[m] * s;
        }

    __nv_bfloat16* Th = (__nv_bfloat16*)smem;   // [128 n][72 m]
    const int mloc = wm * 32 + (lane >> 2);
    const int nbas = wn * 64 + (lane & 3) * 2;
#pragma unroll
    for (int mt = 0; mt < 2; mt++)
#pragma unroll
        for (int jj = 0; jj < 8; jj++)
#pragma unroll
            for (int e = 0; e < 4; e++) {
                int h = e >> 1, col = e & 1;
                float val = fmaxf(acc[mt][jj][e] * sc[mt][h] + bs[mt][h], 0.f);
                int off = (nbas + jj * 8 + col) * 72 + mloc + mt * 16 + h * 8;
                Th[off] = __float2bfloat16(val);
            }
    __syncthreads();

#pragma unroll
    for (int i = 0; i < 8; i++) {
        int idx = tid + i * 128;
        int n = idx >> 3, ch = idx & 7;
        uint4 hv = *(uint4*)&Th[n * 72 + ch * 8];
        size_t dst = ((size_t)b * NSEQ + n0 + n) * CC + m0 + ch * 8;
        *(uint4*)&g_vT_hi[dst] = hv;
    }
}

// =====================================================================
// sim_exp: exp(-kT.qT^T), tile 64x128, 2-PASS (k hi+lo x q_hi only).
// Dropped k_hi*q_lo term: zero-mean ~1e-2 abs on sim, ~5e-5 on output.
// grid (8, 16, BB), 3 CTAs/SM
// =====================================================================
__global__ void __launch_bounds__(128, 3) sim_exp()
{
    extern __shared__ __align__(1024) char smem[];
    const u32 sbase = smem_u32(smem);
    const int tid  = threadIdx.x;
    const int lane = tid & 31;
    const int lr   = lane & 7;
    const int sub  = lane >> 3;
    const int warp = tid >> 5;
    const int wm   = warp >> 1, wn = warp & 1;
    const int b    = blockIdx.z;
    const int dt   = blockIdx.x;
    const int c0   = blockIdx.y * 64;
    const int d0   = dt * 128;

    const __nv_bfloat16* Ah = g_kT_hi + ((size_t)b * CC + c0) * DQ;
    const __nv_bfloat16* Al = g_kT_lo + ((size_t)b * CC + c0) * DQ;
    const __nv_bfloat16* Bh = g_qT_hi + ((size_t)b * CC + d0) * DQ;

    // A hi@0 (8K), A lo@8192, B hi@16384 (16K)
#pragma unroll
    for (int i = 0; i < 4; i++) {
        int idx = tid + i * 128;
        int row = idx >> 3, c = idx & 7;
        u32 dst = sbase + row * 128 + ((c ^ (row & 7)) << 4);
        cp16(dst,        Ah + (size_t)row * DQ + c * 8);
        cp16(dst + 8192, Al + (size_t)row * DQ + c * 8);
    }
#pragma unroll
    for (int i = 0; i < 8; i++) {
        int idx = tid + i * 128;
        int row = idx >> 3, c = idx & 7;
        u32 dst = sbase + 16384 + row * 128 + ((c ^ (row & 7)) << 4);
        cp16(dst, Bh + (size_t)row * DQ + c * 8);
    }
    cp_commit();
    cp_wait0();
    __syncthreads();

    const int a_row = wm * 32 + lr + (sub & 1) * 8;
    const int a_cad = sub >> 1;
    const int b_row = wn * 64 + lr + (sub >> 1) * 8;
    const int b_cad = sub & 1;

    float acc[2][8][4];
#pragma unroll
    for (int i = 0; i < 2; i++)
#pragma unroll
        for (int j = 0; j < 8; j++)
#pragma unroll
            for (int e = 0; e < 4; e++) acc[i][j][e] = 0.f;

#pragma unroll
    for (int kk = 0; kk < 4; kk++) {
        u32 bh[4][4];
#pragma unroll
        for (int np = 0; np < 4; np++) {
            u32 badr = sbase + 16384 + (b_row + np * 16) * 128
                     + (((kk * 2 + b_cad) ^ lr) << 4);
            ldsm4(badr, bh[np][0], bh[np][1], bh[np][2], bh[np][3]);
        }
#pragma unroll
        for (int mt = 0; mt < 2; mt++) {
            u32 ah[4], al[4];
            u32 aadr = sbase + (a_row + mt * 16) * 128
                     + (((kk * 2 + a_cad) ^ lr) << 4);
            ldsm4(aadr,        ah[0], ah[1], ah[2], ah[3]);
            ldsm4(aadr + 8192, al[0], al[1], al[2], al[3]);
#pragma unroll
            for (int np = 0; np < 4; np++) {
                mma_bf16(acc[mt][2 * np],     ah, bh[np][0], bh[np][1]);
                mma_bf16(acc[mt][2 * np + 1], ah, bh[np][2], bh[np][3]);
                mma_bf16(acc[mt][2 * np],     al, bh[np][0], bh[np][1]);
                mma_bf16(acc[mt][2 * np + 1], al, bh[np][2], bh[np][3]);
            }
        }
    }
    __syncthreads();

    __nv_bfloat16* st   = (__nv_bfloat16*)smem;        // [64][144]
    float*         sums = (float*)(smem + 18432);      // [64][2]
    const int grp = lane >> 2, qt = lane & 3;

#pragma unroll
    for (int mt = 0; mt < 2; mt++)
#pragma unroll
        for (int h = 0; h < 2; h++) {
            int r = wm * 32 + mt * 16 + grp + h * 8;
            float s = 0.f;
#pragma unroll
            for (int jj = 0; jj < 8; jj++) {
                float e0 = __expf(-acc[mt][jj][2 * h]);
                float e1 = __expf(-acc[mt][jj][2 * h + 1]);
                s += e0 + e1;
                __nv_bfloat162 p;
                p.x = __float2bfloat16(e0);
                p.y = __float2bfloat16(e1);
                *(__nv_bfloat162*)&st[r * 144 + wn * 64 + jj * 8 + qt * 2] = p;
            }
            s += __shfl_xor_sync(~0u, s, 1);
            s += __shfl_xor_sync(~0u, s, 2);
            if (qt == 0) sums[r * 2 + wn] = s;
        }
    __syncthreads();

    if (tid < 64) {
        float S = sums[tid * 2] + sums[tid * 2 + 1];
        g_psum[((size_t)b * CC + c0 + tid) * 8 + dt] = S;
    }

#pragma unroll
    for (int i = 0; i < 8; i++) {
        int idx = tid + i * 128;
        int row = idx >> 4, ch = idx & 15;
        uint4 v = *(uint4*)&st[row * 144 + ch * 8];
        *(uint4*)&g_aff_hi[((size_t)b * CC + c0 + row) * CC + d0 + ch * 8] = v;
    }
}

// =====================================================================
// out_mma (unchanged from R14)
// =====================================================================
__global__ void __launch_bounds__(128, 4) out_mma(
    float* __restrict__ Cout, const float* __restrict__ xres,
    const float* __restrict__ alpha)
{
    constexpr int STAGE = 24576;
    constexpr int BOFF  = 8192;

    extern __shared__ __align__(1024) char smem[];
    const u32 sbase = smem_u32(smem);
    const int tid = threadIdx.x;
    const int b   = blockIdx.z;
    const int n0  = blockIdx.x * 128;
    const int m0  = blockIdx.y * 64;

    const __nv_bfloat16* A_hi = g_aff_hi + (size_t)b * CC * CC;
    const __nv_bfloat16* B_hi = g_vT_hi + (size_t)b * NSEQ * CC;

    auto load_slab = [&](int k0, int buf) {
        const u32 sb = sbase + buf * STAGE;
#pragma unroll
        for (int i = 0; i < 4; i++) {
            int idx = tid + i * 128;
            int row = idx >> 3, c = idx & 7;
            u32 dst = sb + row * 128 + ((c ^ (row & 7)) << 4);
            cp16(dst, A_hi + (size_t)(m0 + row) * CC + k0 + c * 8);
        }
#pragma unroll
        for (int i = 0; i < 8; i++) {
            int idx = tid + i * 128;
            int row = idx >> 3, c = idx & 7;
            u32 dst = sb + BOFF + row * 128 + ((c ^ (row & 7)) << 4);
            cp16(dst, B_hi + (size_t)(n0 + row) * CC + k0 + c * 8);
        }
        cp_commit();
    };

    const int lane = tid & 31;
    const int lr   = lane & 7;
    const int sub  = lane >> 3;
    const int warp = tid >> 5;
    const int wm   = warp >> 1, wn = warp & 1;

    const int a_row = wm * 32 + lr + (sub & 1) * 8;
    const int a_cad = sub >> 1;
    const int b_row = wn * 64 + lr + (sub >> 1) * 8;
    const int b_cad = sub & 1;

    float acc[2][8][4];
#pragma unroll
    for (int i = 0; i < 2; i++)
#pragma unroll
        for (int j = 0; j < 8; j++)
#pragma unroll
            for (int e = 0; e < 4; e++) acc[i][j][e] = 0.f;

    load_slab(0, 0);

    for (int s = 0; s < 16; s++) {
        if (s + 1 < 16) { load_slab((s + 1) * 64, (s + 1) & 1); cp_wait1(); }
        else            { cp_wait0(); }
        __syncthreads();

        const u32 sb = sbase + (s & 1) * STAGE;
#pragma unroll
        for (int kk = 0; kk < 4; kk++) {
            u32 bh[4][4];
#pragma unroll
            for (int np = 0; np < 4; np++) {
                u32 badr = sb + BOFF + (b_row + np * 16) * 128
                         + (((kk * 2 + b_cad) ^ lr) << 4);
                ldsm4(badr, bh[np][0], bh[np][1], bh[np][2], bh[np][3]);
            }
#pragma unroll
            for (int mt = 0; mt < 2; mt++) {
                u32 ah[4];
                u32 aadr = sb + (a_row + mt * 16) * 128
                         + (((kk * 2 + a_cad) ^ lr) << 4);
                ldsm4(aadr, ah[0], ah[1], ah[2], ah[3]);
#pragma unroll
                for (int np = 0; np < 4; np++) {
                    mma_bf16(acc[mt][2 * np],     ah, bh[np][0], bh[np][1]);
                    mma_bf16(acc[mt][2 * np + 1], ah, bh[np][2], bh[np][3]);
                }
            }
        }
        __syncthreads();
    }

    const float al_ = alpha[0];
    float scl[2][2];
#pragma unroll
    for (int mt = 0; mt < 2; mt++)
#pragma unroll
        for (int h = 0; h < 2; h++) {
            int m = m0 + wm * 32 + mt * 16 + (lane >> 2) + h * 8;
            const float4* p = (const float4*)&g_psum[((size_t)b * CC + m) * 8];
            float4 u = p[0], v = p[1];
            float S = (u.x + u.y) + (u.z + u.w) + (v.x + v.y) + (v.z + v.w);
            scl[mt][h] = al_ / S;
        }
#pragma unroll
    for (int mt = 0; mt < 2; mt++) {
        int m = m0 + wm * 32 + mt * 16 + (lane >> 2);
#pragma unroll
        for (int jj = 0; jj < 8; jj++) {
            int nn = n0 + wn * 64 + (lane & 3) * 2 + jj * 8;
            size_t b0i = ((size_t)b * CC + m) * NSEQ + nn;
            size_t b1i = b0i + 8 * NSEQ;
            float2 x0 = *(const float2*)&xres[b0i];
            float2 x1 = *(const float2*)&xres[b1i];
            float2 o0, o1;
            o0.x = scl[mt][0] * acc[mt][jj][0] + x0.x;
            o0.y = scl[mt][0] * acc[mt][jj][1] + x0.y;
            o1.x = scl[mt][1] * acc[mt][jj][2] + x1.x;
            o1.y = scl[mt][1] * acc[mt][jj][3] + x1.y;
            *(float2*)&Cout[b0i] = o0;
            *(float2*)&Cout[b1i] = o1;
        }
    }
}

// =====================================================================
extern "C" void kernel_launch(void* const* d_in, const int* in_sizes, int n_in,
                              void* d_out, int out_size)
{
    const float* x    = (const float*)d_in[0];
    const float* Wq   = (const float*)d_in[1];
    const float* Wk   = (const float*)d_in[2];
    const float* Wv   = (const float*)d_in[3];
    const float* bn1g = (const float*)d_in[4];
    const float* bn1b = (const float*)d_in[5];
    const float* bn1m = (const float*)d_in[6];
    const float* bn1v = (const float*)d_in[7];
    const float* bn2g = (const float*)d_in[8];
    const float* bn2b = (const float*)d_in[9];
    const float* bn2m = (const float*)d_in[10];
    const float* bn2v = (const float*)d_in[11];
    const float* bn3g = (const float*)d_in[12];
    const float* bn3b = (const float*)d_in[13];
    const float* bn3m = (const float*)d_in[14];
    const float* bn3v = (const float*)d_in[15];
    const float* alpha= (const float*)d_in[16];
    float* out = (float*)d_out;

    static cudaStream_t s1 = nullptr;
    static cudaEvent_t  e0 = nullptr, e1 = nullptr;
    if (s1 == nullptr) {
        cudaStreamCreateWithFlags(&s1, cudaStreamNonBlocking);
        cudaEventCreateWithFlags(&e0, cudaEventDisableTiming);
        cudaEventCreateWithFlags(&e1, cudaEventDisableTiming);
    }

    cudaFuncSetAttribute(qk_mma2, cudaFuncAttributeMaxDynamicSharedMemorySize, 98304);
    cudaFuncSetAttribute(v_mma,   cudaFuncAttributeMaxDynamicSharedMemorySize, 49152);
    cudaFuncSetAttribute(sim_exp, cudaFuncAttributeMaxDynamicSharedMemorySize, 49152);
    cudaFuncSetAttribute(out_mma, cudaFuncAttributeMaxDynamicSharedMemorySize, 49152);

    // main stream: converts
    convert_all<<<9344, 256>>>(x, Wv, Wq, Wk);

    // fork: v on side stream (independent of qk/sim)
    cudaEventRecord(e0, 0);
    cudaStreamWaitEvent(s1, e0, 0);
    v_mma<<<dim3(2, 16, BB), 128, 49152, s1>>>(bn3g, bn3b, bn3m, bn3v);
    cudaEventRecord(e1, s1);

    // main stream: qk -> sim (runs concurrent with v)
    qk_mma2<<<dim3(CC / 128, 2, BB), 128, 98304>>>(
        bn1g, bn1b, bn1m, bn1v, bn2g, bn2b, bn2m, bn2v);
    sim_exp<<<dim3(8, 16, BB), 128, 49152>>>();

    // join: out needs both sim (main) and v (side)
    cudaStreamWaitEvent(0, e1, 0);
    out_mma<<<dim3(2, 16, BB), 128, 49152>>>(out, x, alpha);
}